// round 9
// baseline (speedup 1.0000x reference)
#include <cuda_runtime.h>
#include <mma.h>
#include <math.h>
#include <stdint.h>

using namespace nvcuda;

#define TSZ   512
#define INSZ  1024
#define HIDSZ 1024
#define BH    65536                        // 64*1024
static constexpr size_t TBH = 33554432ull; // 512*64*1024

#define NCTA  64
#define NTHR  256

// Device-global scratch (no allocations allowed)
__device__ float g_gates[3ull * TBH];            // stage1 out [gate][t*64+b][hid]
__device__ float g_Wall[6ull * 1048576];         // tf32 W (stage1 uses slots 3..5)
__device__ float g_Wt2[64ull * 1024 * 48];       // tf32 W_h packed: [cta][k][g*16+i]
__device__ float g_xt[32768ull * 1024];          // tf32 x, time-major [t*64+b][k]
__device__ float g_htT[2][1024 * 64];            // tf32 h transposed [hid][batch]
__device__ unsigned g_flags[NCTA];               // monotonic h-publication flags

// ---------------------------------------------------------------------------
// PTX helpers (baseline sm_90-class PTX only: TMA bulk + mbarrier; no tcgen05)
// ---------------------------------------------------------------------------
__device__ __forceinline__ uint32_t smem_u32(const void* p) {
    uint32_t a;
    asm("{ .reg .u64 t; cvta.to.shared.u64 t, %1; cvt.u32.u64 %0, t; }" : "=r"(a) : "l"(p));
    return a;
}
__device__ __forceinline__ unsigned ld_acq(const unsigned* p) {
    unsigned v;
    asm volatile("ld.acquire.gpu.u32 %0, [%1];" : "=r"(v) : "l"(p) : "memory");
    return v;
}
__device__ __forceinline__ void st_rel(unsigned* p, unsigned v) {
    asm volatile("st.release.gpu.u32 [%0], %1;" :: "l"(p), "r"(v) : "memory");
}
__device__ __forceinline__ void cp16(void* sdst, const void* gsrc) {
    unsigned s = smem_u32(sdst);
    asm volatile("cp.async.cg.shared.global [%0], [%1], 16;" :: "r"(s), "l"(gsrc));
}
#define CP_COMMIT() asm volatile("cp.async.commit_group;")
#define CP_WAIT0()  asm volatile("cp.async.wait_group 0;")

#define MBARRIER_INIT(a, c) \
    asm volatile("mbarrier.init.shared.b64 [%0], %1;" :: "r"(a), "r"(c) : "memory")
#define MBARRIER_EXPECT_TX(a, b) \
    asm volatile("mbarrier.arrive.expect_tx.shared.b64 _, [%0], %1;" :: "r"(a), "r"(b) : "memory")
#define MBARRIER_ARRIVE(a) \
    asm volatile("mbarrier.arrive.shared.b64 _, [%0];" :: "r"(a) : "memory")

__device__ __forceinline__ void mbar_wait(uint32_t mbar, uint32_t parity) {
    asm volatile(
        "{\n\t.reg .pred P1;\n\t"
        "WAIT_LOOP_%=:\n\t"
        "mbarrier.try_wait.parity.acquire.cta.shared::cta.b64 P1, [%0], %1, 0x989680;\n\t"
        "@P1 bra.uni WAIT_DONE_%=;\n\t"
        "bra.uni WAIT_LOOP_%=;\n\t"
        "WAIT_DONE_%=:\n\t}"
        :: "r"(mbar), "r"(parity) : "memory");
}

__device__ __forceinline__ void tma_bulk(uint32_t sdst, const void* gsrc,
                                         uint32_t bytes, uint32_t mbar) {
    asm volatile(
        "cp.async.bulk.shared::cluster.global.mbarrier::complete_tx::bytes "
        "[%0], [%1], %2, [%3];"
        :: "r"(sdst), "l"(gsrc), "r"(bytes), "r"(mbar) : "memory");
}

// ---------------------------------------------------------------------------
// Prep (one launch):
//   [0,3072)      : W_h pack -> g_Wt2[cta][k][g*16+i] (tf32)
//   [3072,6144)   : stage1 W tf32 -> g_Wall[3..5]
//   [6144,38912)  : x tf32 + time-major transpose -> g_xt
// ---------------------------------------------------------------------------
__global__ void prep_kernel(const float* __restrict__ x,
                            const float* __restrict__ Wir, const float* __restrict__ Wiz,
                            const float* __restrict__ Win, const float* __restrict__ Whr,
                            const float* __restrict__ Whz, const float* __restrict__ Whn) {
    const int bid = blockIdx.x, tid = threadIdx.x;
    if (bid < 3072) {                               // W_h pack, one k-row per block
        int g = bid >> 10;
        int k = bid & 1023;
        const float* W = (g == 0) ? Whr : ((g == 1) ? Whz : Whn);
        int col = tid << 2;                         // 0,4,...,1020
        float4 v = *(const float4*)(W + (size_t)k * 1024 + col);
        v.x = wmma::__float_to_tf32(v.x); v.y = wmma::__float_to_tf32(v.y);
        v.z = wmma::__float_to_tf32(v.z); v.w = wmma::__float_to_tf32(v.w);
        int cta = col >> 4, i = col & 15;
        *(float4*)(g_Wt2 + (size_t)cta * 49152 + (size_t)k * 48 + g * 16 + i) = v;
    } else if (bid < 6144) {                        // stage1 W tf32 copy
        int b2 = bid - 3072;
        int which = b2 >> 10;
        int o = (b2 & 1023) * 256 + tid;
        const float* src = (which == 0) ? Wir : ((which == 1) ? Wiz : Win);
        float4 v = ((const float4*)src)[o];
        v.x = wmma::__float_to_tf32(v.x); v.y = wmma::__float_to_tf32(v.y);
        v.z = wmma::__float_to_tf32(v.z); v.w = wmma::__float_to_tf32(v.w);
        ((float4*)(g_Wall + (size_t)(3 + which) * 1048576))[o] = v;
    } else {                                        // x transpose + tf32
        int m = bid - 6144;
        int t = m >> 6, b = m & 63;
        float4 v = ((const float4*)(x + ((size_t)b * TSZ + t) * INSZ))[tid];
        v.x = wmma::__float_to_tf32(v.x); v.y = wmma::__float_to_tf32(v.y);
        v.z = wmma::__float_to_tf32(v.z); v.w = wmma::__float_to_tf32(v.w);
        ((float4*)(g_xt + (size_t)m * 1024))[tid] = v;
    }
}

// ---------------------------------------------------------------------------
// Stage 1 (wmma, unchanged): gates[g][m][n] = xt[m,:] @ W_g[:,n]
// ---------------------------------------------------------------------------
#define S1_SMEM 54272

__global__ __launch_bounds__(256)
void stage1_kernel() {
    extern __shared__ __align__(16) float s1[];
    const int gate = blockIdx.x >> 4;
    const int col0 = (blockIdx.x & 15) << 6;
    const int m0   = blockIdx.y << 7;
    const float* Wp = g_Wall + (size_t)(3 + gate) * 1048576;

    const int tid  = threadIdx.x;
    const int wid  = tid >> 5;
    const int mrow = wid & 3;
    const int ncol = wid >> 2;

    wmma::fragment<wmma::accumulator, 16, 16, 8, float> acc[2][2];
#pragma unroll
    for (int i = 0; i < 2; i++)
#pragma unroll
        for (int j = 0; j < 2; j++) wmma::fill_fragment(acc[i][j], 0.0f);

#define S1_ISSUE(c)                                                             \
    {                                                                           \
        float* As = s1 + ((c) & 1) * 6784;                                      \
        float* Bs = As + 4608;                                                  \
        _Pragma("unroll")                                                       \
        for (int q = 0; q < 4; q++) {                                           \
            int o = tid + q * 256;                                              \
            int row = o >> 3, c4 = (o & 7) << 2;                                \
            cp16(As + row * 36 + c4,                                            \
                 g_xt + (size_t)(m0 + row) * 1024 + (c) * 32 + c4);             \
        }                                                                       \
        _Pragma("unroll")                                                       \
        for (int q = 0; q < 2; q++) {                                           \
            int o = tid + q * 256;                                              \
            int row = o >> 4, c4 = (o & 15) << 2;                               \
            cp16(Bs + row * 68 + c4,                                            \
                 Wp + (size_t)((c) * 32 + row) * 1024 + col0 + c4);             \
        }                                                                       \
    }

    S1_ISSUE(0); CP_COMMIT();

    for (int c = 0; c < 32; c++) {
        CP_WAIT0();
        __syncthreads();
        if (c < 31) { S1_ISSUE(c + 1); CP_COMMIT(); }

        const float* As = s1 + (c & 1) * 6784;
        const float* Bs = As + 4608;
#pragma unroll
        for (int kk = 0; kk < 4; kk++) {
            wmma::fragment<wmma::matrix_a, 16, 16, 8, wmma::precision::tf32, wmma::row_major> a0, a1;
            wmma::load_matrix_sync(a0, As + (mrow * 32) * 36 + kk * 8, 36);
            wmma::load_matrix_sync(a1, As + (mrow * 32 + 16) * 36 + kk * 8, 36);
            wmma::fragment<wmma::matrix_b, 16, 16, 8, wmma::precision::tf32, wmma::row_major> b0, b1;
            wmma::load_matrix_sync(b0, Bs + (kk * 8) * 68 + ncol * 32, 68);
            wmma::load_matrix_sync(b1, Bs + (kk * 8) * 68 + ncol * 32 + 16, 68);
            wmma::mma_sync(acc[0][0], a0, b0, acc[0][0]);
            wmma::mma_sync(acc[0][1], a0, b1, acc[0][1]);
            wmma::mma_sync(acc[1][0], a1, b0, acc[1][0]);
            wmma::mma_sync(acc[1][1], a1, b1, acc[1][1]);
        }
        __syncthreads();
    }
#undef S1_ISSUE

#pragma unroll
    for (int mi = 0; mi < 2; mi++)
#pragma unroll
        for (int ni = 0; ni < 2; ni++)
            wmma::store_matrix_sync(
                g_gates + (size_t)gate * TBH
                        + (size_t)(m0 + mrow * 32 + mi * 16) * 1024
                        + col0 + ncol * 32 + ni * 16,
                acc[mi][ni], 1024, wmma::mem_row_major);
}

// ---------------------------------------------------------------------------
// Persistent recurrence v4: TMA-bulk loads + wmma compute.
// 64 CTAs x 256 thr. CTA c owns out cols [16c,16c+16) of all 3 gates.
// Per step: [64x1024] @ [1024x48], 32 K-chunks of 32, 4-stage mbarrier pipe.
// Per chunk: 2 cp.async.bulk (A: 32k x 64m = 8KB from g_htT; B: 32k x 48n = 6KB
// from g_Wt2), issued by thread 0 with lookahead 2.
// 8 warps = 2 mpair(32 rows) x 4 kquarter(8 k of each chunk); A read col_major.
// Smem 107776 B:
//   [0..1024)        mbarriers: full[4]@i*8, empty[4]@64+i*8
//   [1024..33792)    A stages 4 x 8192
//   [33792..58368)   B stages 4 x 6144
//   [58368..95232)   red[3][64][48]
//   [95232..107520)  pre[64][48]
//   [107520..107776) sbias[4][16]
// ---------------------------------------------------------------------------
#define REC_SMEM   107776
#define OFF_FULL(i)  ((i) * 8)
#define OFF_EMPTY(i) (64 + (i) * 8)
#define OFF_A        1024
#define OFF_B        33792
#define OFF_RED      58368
#define OFF_PRE      95232
#define OFF_BIAS     107520

__global__ __launch_bounds__(NTHR, 1)
void recur_kernel(const float* __restrict__ b_ir, const float* __restrict__ b_hr,
                  const float* __restrict__ b_iz, const float* __restrict__ b_hz,
                  const float* __restrict__ b_in, const float* __restrict__ b_hn,
                  float* __restrict__ out, int write_hfinal) {
    extern __shared__ __align__(1024) char smem[];
    const uint32_t sb = smem_u32(smem);
    float* red   = (float*)(smem + OFF_RED);
    float* pre   = (float*)(smem + OFF_PRE);
    float* sbias = (float*)(smem + OFF_BIAS);

    const int tid   = threadIdx.x;
    const int wid   = tid >> 5;
    const int lane  = tid & 31;
    const int cta   = blockIdx.x;
    const int col0  = cta << 4;
    const int mpair = wid & 1;           // rows [32*mpair, +32)
    const int kq    = wid >> 1;          // k-step within chunk: rows [8kq, 8kq+8)

    if (tid == 0) {
#pragma unroll
        for (int s = 0; s < 4; s++) {
            MBARRIER_INIT(sb + OFF_FULL(s), 1);
            MBARRIER_INIT(sb + OFF_EMPTY(s), 8);
        }
    }
    if (tid < 64) {                      // biases [br_tot, bz_tot, b_in, b_hn][16]
        int a = tid >> 4, i = tid & 15, jc = col0 + i;
        float v = (a == 0) ? (b_ir[jc] + b_hr[jc])
                : (a == 1) ? (b_iz[jc] + b_hz[jc])
                : (a == 2) ? b_in[jc] : b_hn[jc];
        sbias[a * 16 + i] = v;
    }
    __syncthreads();

    const unsigned base = *(volatile unsigned*)&g_flags[cta];

    // pointwise ownership: col jcol, 4 consecutive rows
    const int c_pb = tid & 15;
    const int r4   = (tid >> 4) << 2;    // rows r4..r4+3
    const int jcol = col0 + c_pb;

    float pg_r[4], pg_z[4], pg_n[4];
    float hpq[4] = {0.f, 0.f, 0.f, 0.f};
#pragma unroll
    for (int q = 0; q < 4; q++) {
        size_t gi = (size_t)(r4 + q) * 1024 + jcol;
        pg_r[q] = g_gates[gi];
        pg_z[q] = g_gates[TBH + gi];
        pg_n[q] = g_gates[2ull * TBH + gi];
    }

    for (int t = 0; t < TSZ; t++) {
        if (t > 0) {
            const unsigned tgt = base + (unsigned)t;
            const float* hsrc = g_htT[(t - 1) & 1];
            const float* wsrc = g_Wt2 + (size_t)cta * 49152;

            wmma::fragment<wmma::accumulator, 16, 16, 8, float> acc[2][3];
#pragma unroll
            for (int mi = 0; mi < 2; mi++)
#pragma unroll
                for (int g = 0; g < 3; g++) wmma::fill_fragment(acc[mi][g], 0.0f);

            // producer issue for chunk ci (thread 0 only)
#define R_ISSUE(ci)                                                             \
            {                                                                   \
                int s_ = (ci) & 3;                                              \
                int u_ = (ci) >> 2;                                             \
                if (!(t == 1 && (ci) < 4))                                      \
                    mbar_wait(sb + OFF_EMPTY(s_), (u_ + 1) & 1);                \
                while ((int)(ld_acq(&g_flags[2 * (ci)]) - tgt) < 0) { }         \
                while ((int)(ld_acq(&g_flags[2 * (ci) + 1]) - tgt) < 0) { }     \
                MBARRIER_EXPECT_TX(sb + OFF_FULL(s_), 14336u);                  \
                tma_bulk(sb + OFF_A + s_ * 8192, hsrc + (ci) * 2048, 8192u,     \
                         sb + OFF_FULL(s_));                                    \
                tma_bulk(sb + OFF_B + s_ * 6144, wsrc + (ci) * 1536, 6144u,     \
                         sb + OFF_FULL(s_));                                    \
            }

            if (tid == 0) { R_ISSUE(0); R_ISSUE(1); }

            for (int c = 0; c < 32; c++) {
                if (tid == 0 && c + 2 < 32) R_ISSUE(c + 2);

                const int s = c & 3;
                mbar_wait(sb + OFF_FULL(s), (c >> 2) & 1);

                const float* sA = (const float*)(smem + OFF_A + s * 8192);  // [32k][64m]
                const float* sB = (const float*)(smem + OFF_B + s * 6144);  // [32k][48n]

                wmma::fragment<wmma::matrix_a, 16, 16, 8, wmma::precision::tf32, wmma::col_major> a0, a1;
                wmma::load_matrix_sync(a0, sA + (kq * 8) * 64 + mpair * 32, 64);
                wmma::load_matrix_sync(a1, sA + (kq * 8) * 64 + mpair * 32 + 16, 64);
#pragma unroll
                for (int g = 0; g < 3; g++) {
                    wmma::fragment<wmma::matrix_b, 16, 16, 8, wmma::precision::tf32, wmma::row_major> bf;
                    wmma::load_matrix_sync(bf, sB + (kq * 8) * 48 + g * 16, 48);
                    wmma::mma_sync(acc[0][g], a0, bf, acc[0][g]);
                    wmma::mma_sync(acc[1][g], a1, bf, acc[1][g]);
                }

                if (lane == 0) MBARRIER_ARRIVE(sb + OFF_EMPTY(s));
            }
#undef R_ISSUE

            __syncthreads();
            // 4-way K reduction: kq 1..3 publish, kq 0 combines -> pre
            if (kq > 0) {
                float* sdst = red + (size_t)(kq - 1) * 3072;
#pragma unroll
                for (int mi = 0; mi < 2; mi++)
#pragma unroll
                    for (int g = 0; g < 3; g++)
                        wmma::store_matrix_sync(sdst + (mpair * 32 + mi * 16) * 48 + g * 16,
                                                acc[mi][g], 48, wmma::mem_row_major);
            }
            __syncthreads();
            if (kq == 0) {
#pragma unroll
                for (int src = 0; src < 3; src++) {
                    const float* ssrc = red + (size_t)src * 3072;
#pragma unroll
                    for (int mi = 0; mi < 2; mi++)
#pragma unroll
                        for (int g = 0; g < 3; g++) {
                            wmma::fragment<wmma::accumulator, 16, 16, 8, float> p;
                            wmma::load_matrix_sync(p, ssrc + (mpair * 32 + mi * 16) * 48 + g * 16,
                                                   48, wmma::mem_row_major);
#pragma unroll
                            for (int e = 0; e < p.num_elements; e++)
                                acc[mi][g].x[e] += p.x[e];
                        }
                }
#pragma unroll
                for (int mi = 0; mi < 2; mi++)
#pragma unroll
                    for (int g = 0; g < 3; g++)
                        wmma::store_matrix_sync(pre + (mpair * 32 + mi * 16) * 48 + g * 16,
                                                acc[mi][g], 48, wmma::mem_row_major);
            }
            __syncthreads();
        }

        // ---------------- pointwise GRU update ----------------
        {
            const size_t toff = (size_t)t * BH;
            float hv[4];
#pragma unroll
            for (int q = 0; q < 4; q++) {
                int row = r4 + q;
                float gr = pg_r[q] + sbias[c_pb];
                float gz = pg_z[q] + sbias[16 + c_pb];
                float gn = pg_n[q] + sbias[32 + c_pb];
                float hnb = sbias[48 + c_pb];
                if (t > 0) {
                    gr  += pre[row * 48 + c_pb];
                    gz  += pre[row * 48 + 16 + c_pb];
                    hnb += pre[row * 48 + 32 + c_pb];
                }
                float r = 1.0f / (1.0f + expf(-gr));
                float z = 1.0f / (1.0f + expf(-gz));
                float n = tanhf(gn + r * hnb);
                hv[q] = (1.0f - z) * n + z * hpq[q];
                hpq[q] = hv[q];
                out[toff + (size_t)row * 1024 + jcol] = hv[q];
            }
            // transposed tf32 h for next step's TMA (contiguous float4)
            float4 w = make_float4(wmma::__float_to_tf32(hv[0]), wmma::__float_to_tf32(hv[1]),
                                   wmma::__float_to_tf32(hv[2]), wmma::__float_to_tf32(hv[3]));
            *(float4*)(&g_htT[t & 1][(size_t)jcol * 64 + r4]) = w;

            if (t == TSZ - 1 && write_hfinal) {
#pragma unroll
                for (int q = 0; q < 4; q++)
                    out[TBH + (size_t)(r4 + q) * 1024 + jcol] = hv[q];
            }
        }

        __syncthreads();
        if (tid == 0) st_rel(&g_flags[cta], base + (unsigned)t + 1u);

        if (t < TSZ - 1) {          // prefetch next step's gates (overlaps ramp)
            const size_t toff1 = (size_t)(t + 1) * BH;
#pragma unroll
            for (int q = 0; q < 4; q++) {
                size_t gi = toff1 + (size_t)(r4 + q) * 1024 + jcol;
                pg_r[q] = g_gates[gi];
                pg_z[q] = g_gates[TBH + gi];
                pg_n[q] = g_gates[2ull * TBH + gi];
            }
        }
        __syncthreads();
    }
}

// ---------------------------------------------------------------------------
extern "C" void kernel_launch(void* const* d_in, const int* in_sizes, int n_in,
                              void* d_out, int out_size) {
    const float* x    = (const float*)d_in[0];
    const float* W_ir = (const float*)d_in[1];
    const float* b_ir = (const float*)d_in[2];
    const float* W_hr = (const float*)d_in[3];
    const float* b_hr = (const float*)d_in[4];
    const float* W_iz = (const float*)d_in[5];
    const float* b_iz = (const float*)d_in[6];
    const float* W_hz = (const float*)d_in[7];
    const float* b_hz = (const float*)d_in[8];
    const float* W_in = (const float*)d_in[9];
    const float* b_in = (const float*)d_in[10];
    const float* W_hn = (const float*)d_in[11];
    const float* b_hn = (const float*)d_in[12];
    float* out = (float*)d_out;

    const int has_hfinal = ((size_t)out_size >= TBH + (size_t)BH) ? 1 : 0;

    static bool init_done = false;
    if (!init_done) {
        cudaFuncSetAttribute(recur_kernel,
                             cudaFuncAttributeMaxDynamicSharedMemorySize, REC_SMEM);
        cudaFuncSetAttribute(stage1_kernel,
                             cudaFuncAttributeMaxDynamicSharedMemorySize, S1_SMEM);
        init_done = true;
    }

    prep_kernel<<<38912, 256>>>(x, W_ir, W_iz, W_in, W_hr, W_hz, W_hn);
    stage1_kernel<<<dim3(48, 256), 256, S1_SMEM>>>();
    recur_kernel<<<NCTA, NTHR, REC_SMEM>>>(b_ir, b_hr, b_iz, b_hz, b_in, b_hn,
                                           out, has_hfinal);
}

// round 11
// speedup vs baseline: 1.7458x; 1.7458x over previous
#include <cuda_runtime.h>
#include <mma.h>
#include <math.h>
#include <stdint.h>

using namespace nvcuda;

#define TSZ   512
#define INSZ  1024
#define HIDSZ 1024
#define BH    65536                        // 64*1024
static constexpr size_t TBH = 33554432ull; // 512*64*1024

#define NREC  64                           // recurrence CTAs
#define NS1   80                           // stage1 worker CTAs
#define NTOT  144
#define NTHR  512

// Device-global scratch (no allocations allowed)
__device__ float g_gates[3ull * TBH];           // [gate][t*64+b][hid]
__device__ float g_Wall[6ull * 1048576];        // tf32 W: [hr|hz|hn|ir|iz|in]
__device__ float g_xt[32768ull * 1024];         // tf32 x, time-major [t*64+b][k]
__device__ float g_ht[2][BH];                   // tf32 h ping-pong
__device__ unsigned g_bar_cnt = 0;              // grid barrier (recur CTAs only)
__device__ unsigned g_bar_gen = 0;
__device__ unsigned g_mt_cnt[256];              // stage1 per-mtile counters (monotonic)

// ---------------------------------------------------------------------------
__device__ __forceinline__ unsigned ld_acq(const unsigned* p) {
    unsigned v;
    asm volatile("ld.acquire.gpu.u32 %0, [%1];" : "=r"(v) : "l"(p) : "memory");
    return v;
}
__device__ __forceinline__ void st_rel(unsigned* p, unsigned v) {
    asm volatile("st.release.gpu.u32 [%0], %1;" :: "l"(p), "r"(v) : "memory");
}
__device__ __forceinline__ void red_rel_add(unsigned* p) {
    asm volatile("red.release.gpu.global.add.u32 [%0], %1;" :: "l"(p), "r"(1u) : "memory");
}
__device__ __forceinline__ void cp16(void* sdst, const void* gsrc) {
    unsigned s;
    asm("{ .reg .u64 t; cvta.to.shared.u64 t, %1; cvt.u32.u64 %0, t; }" : "=r"(s) : "l"(sdst));
    asm volatile("cp.async.cg.shared.global [%0], [%1], 16;" :: "r"(s), "l"(gsrc));
}
#define CP_COMMIT() asm volatile("cp.async.commit_group;")
#define CP_WAIT0()  asm volatile("cp.async.wait_group 0;")

// ---------------------------------------------------------------------------
// Prep: tf32 weights -> g_Wall[0..5] (hr,hz,hn,ir,iz,in); x tf32 + transpose.
// ---------------------------------------------------------------------------
__global__ void prep_kernel(const float* __restrict__ x,
                            const float* __restrict__ Whr, const float* __restrict__ Whz,
                            const float* __restrict__ Whn, const float* __restrict__ Wir,
                            const float* __restrict__ Wiz, const float* __restrict__ Win) {
    const int bid = blockIdx.x, tid = threadIdx.x;
    if (bid < 6144) {
        int which = bid >> 10;
        int o = (bid & 1023) * 256 + tid;
        const float* src = (which == 0) ? Whr : (which == 1) ? Whz : (which == 2) ? Whn
                         : (which == 3) ? Wir : (which == 4) ? Wiz : Win;
        float4 v = ((const float4*)src)[o];
        v.x = wmma::__float_to_tf32(v.x); v.y = wmma::__float_to_tf32(v.y);
        v.z = wmma::__float_to_tf32(v.z); v.w = wmma::__float_to_tf32(v.w);
        ((float4*)(g_Wall + (size_t)which * 1048576))[o] = v;
    } else {
        int m = bid - 6144;                     // 0..32767, m = t*64+b
        int t = m >> 6, b = m & 63;
        float4 v = ((const float4*)(x + ((size_t)b * TSZ + t) * INSZ))[tid];
        v.x = wmma::__float_to_tf32(v.x); v.y = wmma::__float_to_tf32(v.y);
        v.z = wmma::__float_to_tf32(v.z); v.w = wmma::__float_to_tf32(v.w);
        ((float4*)(g_xt + (size_t)m * 1024))[tid] = v;
    }
}

// ---------------------------------------------------------------------------
// Fused persistent kernel, grid 144 x 512:
//   CTAs [0,64):  recurrence (owner-computes: CTA c owns cols [16c,16c+16)
//                 of all 3 gates). 16 warps = 8 kgrp(K=128) x 2 mpair(32 rows).
//   CTAs [64,144): stage1 workers. Unit u = mtile*48 + sub (sub = gate*16+coltile).
//                 Publish g_mt_cnt[mtile] via release-add (+48/replay, monotonic).
// Recurrence dyn smem (floats; all strides 16B-aligned):
//   hb  @0      : 2 stages x 8 kgrp x [64][20]   (20480 fl)   | pre aliases [0,3072)
//   Wb  @20480  : 2 stages x 8 kgrp x [16][52]   (13312 fl)
//   red @33792  : 7 x [64][48]                   (21504 fl)
//   bias@55296  : [4][16]                        (64 fl)
// Total 55360 fl = 221440 B. Stage1 path uses sm[0..13568).
// ---------------------------------------------------------------------------
#define FUSED_SMEM 221440

__global__ __launch_bounds__(NTHR, 1)
void fused_kernel(const float* __restrict__ b_ir, const float* __restrict__ b_hr,
                  const float* __restrict__ b_iz, const float* __restrict__ b_hz,
                  const float* __restrict__ b_in, const float* __restrict__ b_hn,
                  float* __restrict__ out, int write_hfinal) {
    extern __shared__ __align__(16) float sm[];
    const int cta = blockIdx.x;
    const int tid = threadIdx.x;
    const int wid = tid >> 5;

    if (cta >= NREC) {
        // ==================== STAGE1 WORKER ====================
        const int worker = cta - NREC;
        const int mrow = wid & 3;            // rows [32*mrow, +32)
        const int ncol = wid >> 2;           // cols [16*ncol, +16)

        for (int u = worker; u < 12288; u += NS1) {
            const int mtile = u / 48;
            const int sub   = u - mtile * 48;
            const int gate  = sub >> 4;
            const int col0s = (sub & 15) << 6;
            const int m0    = mtile << 7;
            const float* Wp = g_Wall + (size_t)(3 + gate) * 1048576;

            wmma::fragment<wmma::accumulator, 16, 16, 8, float> acc0, acc1;
            wmma::fill_fragment(acc0, 0.0f);
            wmma::fill_fragment(acc1, 0.0f);

#define S1_ISSUE(c)                                                             \
            {                                                                   \
                float* As = sm + ((c) & 1) * 6784;                              \
                float* Bs = As + 4608;                                          \
                _Pragma("unroll")                                               \
                for (int q = 0; q < 2; q++) {                                   \
                    int o = tid + q * 512;                                      \
                    int row = o >> 3, c4 = (o & 7) << 2;                        \
                    cp16(As + row * 36 + c4,                                    \
                         g_xt + (size_t)(m0 + row) * 1024 + (c) * 32 + c4);     \
                }                                                               \
                {                                                               \
                    int row = tid >> 4, c4 = (tid & 15) << 2;                   \
                    cp16(Bs + row * 68 + c4,                                    \
                         Wp + (size_t)((c) * 32 + row) * 1024 + col0s + c4);    \
                }                                                               \
            }

            S1_ISSUE(0); CP_COMMIT();
            for (int c = 0; c < 32; c++) {
                CP_WAIT0();
                __syncthreads();
                if (c < 31) { S1_ISSUE(c + 1); CP_COMMIT(); }

                const float* As = sm + (c & 1) * 6784;
                const float* Bs = As + 4608;
#pragma unroll
                for (int kk = 0; kk < 4; kk++) {
                    wmma::fragment<wmma::matrix_a, 16, 16, 8, wmma::precision::tf32, wmma::row_major> a0, a1;
                    wmma::load_matrix_sync(a0, As + (mrow * 32) * 36 + kk * 8, 36);
                    wmma::load_matrix_sync(a1, As + (mrow * 32 + 16) * 36 + kk * 8, 36);
                    wmma::fragment<wmma::matrix_b, 16, 16, 8, wmma::precision::tf32, wmma::row_major> bf;
                    wmma::load_matrix_sync(bf, Bs + (kk * 8) * 68 + ncol * 16, 68);
                    wmma::mma_sync(acc0, a0, bf, acc0);
                    wmma::mma_sync(acc1, a1, bf, acc1);
                }
                __syncthreads();
            }
#undef S1_ISSUE

            wmma::store_matrix_sync(
                g_gates + (size_t)gate * TBH + (size_t)(m0 + mrow * 32) * 1024 + col0s + ncol * 16,
                acc0, 1024, wmma::mem_row_major);
            wmma::store_matrix_sync(
                g_gates + (size_t)gate * TBH + (size_t)(m0 + mrow * 32 + 16) * 1024 + col0s + ncol * 16,
                acc1, 1024, wmma::mem_row_major);

            __syncthreads();
            if (tid == 0) red_rel_add(&g_mt_cnt[mtile]);
        }
        return;
    }

    // ==================== RECURRENCE ====================
    float* hb    = sm;                 // 2*8*[64][20]; 'pre' aliases sm[0..3072)
    float* Wb    = sm + 20480;         // 2*8*[16][52]
    float* red   = sm + 33792;         // 7*[64][48]
    float* sbias = sm + 55296;         // [4][16]
    float* pre   = sm;

    const int kgrp  = wid >> 1;          // 0..7, K range [kgrp*128, +128)
    const int mpair = wid & 1;           // rows [32*mpair, +32)
    const int col0  = cta << 4;

    __shared__ unsigned s_gen0;
    if (tid == 0) s_gen0 = *(volatile unsigned*)&g_bar_gen;
    if (tid < 64) {                      // [br_tot, bz_tot, b_in, b_hn][16]
        int a = tid >> 4, i = tid & 15, jc = col0 + i;
        float v = (a == 0) ? (b_ir[jc] + b_hr[jc])
                : (a == 1) ? (b_iz[jc] + b_hz[jc])
                : (a == 2) ? b_in[jc] : b_hn[jc];
        sbias[a * 16 + i] = v;
    }
    const unsigned s1base = *(volatile unsigned*)&g_mt_cnt[255];  // settled value
    __syncthreads();
    const unsigned gen0 = s_gen0;

    // pointwise ownership: col jcol, rows r2, r2+1
    const int c_pb = tid & 15;
    const int r2   = (tid >> 4) << 1;
    const int jcol = col0 + c_pb;

    float pg_r[2], pg_z[2], pg_n[2];
    float hpq[2] = {0.f, 0.f};

    // wait for stage1 to finish mtile 0 (gates for t=0,1), then prefetch t=0
    if (tid == 1) {
        while ((int)(ld_acq(&g_mt_cnt[0]) - (s1base + 48u)) < 0) { }
    }
    __syncthreads();
#pragma unroll
    for (int q = 0; q < 2; q++) {
        size_t gi = (size_t)(r2 + q) * 1024 + jcol;
        pg_r[q] = g_gates[gi];
        pg_z[q] = g_gates[TBH + gi];
        pg_n[q] = g_gates[2ull * TBH + gi];
    }

    for (int t = 0; t < TSZ; t++) {
        if (t > 0) {
            // ===== Phase A: hW [64 x 48] = h_{t-1} @ [Whr|Whz|Whn] cols =====
            const float* hsrc = g_ht[(t - 1) & 1];

            wmma::fragment<wmma::accumulator, 16, 16, 8, float> acc[2][3];
#pragma unroll
            for (int mi = 0; mi < 2; mi++)
#pragma unroll
                for (int g = 0; g < 3; g++) wmma::fill_fragment(acc[mi][g], 0.0f);

#define R_ISSUE(c)                                                              \
            {                                                                   \
                int kofs = (c) * 16;                                            \
                _Pragma("unroll")                                               \
                for (int q = 0; q < 4; q++) {                                   \
                    int o = tid + q * 512;                                      \
                    int kg = o >> 8, idx = o & 255;                             \
                    int row = idx >> 2, c4 = (idx & 3) << 2;                    \
                    cp16(hb + (((c) & 1) * 8 + kg) * 1280 + row * 20 + c4,      \
                         hsrc + (size_t)row * 1024 + kg * 128 + kofs + c4);     \
                }                                                               \
                _Pragma("unroll")                                               \
                for (int q = 0; q < 3; q++) {                                   \
                    int o = tid + q * 512;                                      \
                    int kg = o / 192, idx = o % 192;                            \
                    int row = idx / 12, cw = (idx % 12) << 2;                   \
                    int gate = cw >> 4;                                         \
                    cp16(Wb + (((c) & 1) * 8 + kg) * 832 + row * 52 + cw,       \
                         g_Wall + (size_t)gate * 1048576                        \
                                + (size_t)(kg * 128 + kofs + row) * 1024        \
                                + col0 + (cw & 15));                            \
                }                                                               \
            }

            R_ISSUE(0); CP_COMMIT();

            for (int it = 0; it < 8; it++) {
                CP_WAIT0();
                __syncthreads();
                if (it < 7) { R_ISSUE(it + 1); CP_COMMIT(); }

                const float* A = hb + ((it & 1) * 8 + kgrp) * 1280 + (mpair * 32) * 20;
                const float* B = Wb + ((it & 1) * 8 + kgrp) * 832;
#pragma unroll
                for (int kk = 0; kk < 2; kk++) {
                    wmma::fragment<wmma::matrix_a, 16, 16, 8, wmma::precision::tf32, wmma::row_major> a0, a1;
                    wmma::load_matrix_sync(a0, A + kk * 8, 20);
                    wmma::load_matrix_sync(a1, A + 16 * 20 + kk * 8, 20);
#pragma unroll
                    for (int g = 0; g < 3; g++) {
                        wmma::fragment<wmma::matrix_b, 16, 16, 8, wmma::precision::tf32, wmma::row_major> bf;
                        wmma::load_matrix_sync(bf, B + (kk * 8) * 52 + g * 16, 52);
                        wmma::mma_sync(acc[0][g], a0, bf, acc[0][g]);
                        wmma::mma_sync(acc[1][g], a1, bf, acc[1][g]);
                    }
                }
                __syncthreads();
            }
#undef R_ISSUE

            // 8-way K reduction: kgrp 1..7 publish, kgrp 0 combines -> pre
            if (kgrp > 0) {
                float* s = red + (size_t)(kgrp - 1) * 3072;
#pragma unroll
                for (int mi = 0; mi < 2; mi++)
#pragma unroll
                    for (int g = 0; g < 3; g++)
                        wmma::store_matrix_sync(s + (mpair * 32 + mi * 16) * 48 + g * 16,
                                                acc[mi][g], 48, wmma::mem_row_major);
            }
            __syncthreads();
            if (kgrp == 0) {
#pragma unroll
                for (int src = 0; src < 7; src++) {
                    const float* s = red + (size_t)src * 3072;
#pragma unroll
                    for (int mi = 0; mi < 2; mi++)
#pragma unroll
                        for (int g = 0; g < 3; g++) {
                            wmma::fragment<wmma::accumulator, 16, 16, 8, float> p;
                            wmma::load_matrix_sync(p, s + (mpair * 32 + mi * 16) * 48 + g * 16,
                                                   48, wmma::mem_row_major);
#pragma unroll
                            for (int e = 0; e < p.num_elements; e++) acc[mi][g].x[e] += p.x[e];
                        }
                }
#pragma unroll
                for (int mi = 0; mi < 2; mi++)
#pragma unroll
                    for (int g = 0; g < 3; g++)
                        wmma::store_matrix_sync(pre + (mpair * 32 + mi * 16) * 48 + g * 16,
                                                acc[mi][g], 48, wmma::mem_row_major);
            }
            __syncthreads();
        }

        // ===== Phase B: pointwise =====
        {
            const size_t toff = (size_t)t * BH;
#pragma unroll
            for (int q = 0; q < 2; q++) {
                int row = r2 + q;
                float gr = pg_r[q] + sbias[c_pb];
                float gz = pg_z[q] + sbias[16 + c_pb];
                float gn = pg_n[q] + sbias[32 + c_pb];
                float hn = sbias[48 + c_pb];
                if (t > 0) {
                    gr += pre[row * 48 + c_pb];
                    gz += pre[row * 48 + 16 + c_pb];
                    hn += pre[row * 48 + 32 + c_pb];
                }
                float r = 1.0f / (1.0f + expf(-gr));
                float z = 1.0f / (1.0f + expf(-gz));
                float n = tanhf(gn + r * hn);
                float hnew = (1.0f - z) * n + z * hpq[q];
                hpq[q] = hnew;
                out[toff + (size_t)row * 1024 + jcol] = hnew;
                g_ht[t & 1][(size_t)row * 1024 + jcol] = wmma::__float_to_tf32(hnew);
                if (t == TSZ - 1 && write_hfinal)
                    out[TBH + (size_t)row * 1024 + jcol] = hnew;
            }
        }

        if (t == TSZ - 1) break;

        // ===== split grid barrier + stage1 poll + gate prefetch =====
        __syncthreads();
        const unsigned target = gen0 + (unsigned)t + 1u;
        bool released = false;
        if (tid == 0) {
            unsigned old;
            asm volatile("atom.acq_rel.gpu.add.u32 %0, [%1], %2;"
                         : "=r"(old) : "l"(&g_bar_cnt), "r"(1u) : "memory");
            if (old == NREC - 1u) {
                asm volatile("st.relaxed.gpu.u32 [%0], %1;" :: "l"(&g_bar_cnt), "r"(0u) : "memory");
                st_rel(&g_bar_gen, target);
                released = true;
            }
        }
        if (tid == 1) {                      // gates for t+1 ready?
            int mt = (t + 1) >> 1;
            while ((int)(ld_acq(&g_mt_cnt[mt]) - (s1base + 48u)) < 0) { }
        }
        __syncthreads();
        {
            const size_t toff1 = (size_t)(t + 1) * BH;
#pragma unroll
            for (int q = 0; q < 2; q++) {
                size_t gi = toff1 + (size_t)(r2 + q) * 1024 + jcol;
                pg_r[q] = g_gates[gi];
                pg_z[q] = g_gates[TBH + gi];
                pg_n[q] = g_gates[2ull * TBH + gi];
            }
        }
        if (tid == 0 && !released) {
            unsigned v;
            do {
                asm volatile("ld.acquire.gpu.u32 %0, [%1];" : "=r"(v) : "l"(&g_bar_gen) : "memory");
            } while ((int)(v - target) < 0);
        }
        __syncthreads();
    }
}

// ---------------------------------------------------------------------------
extern "C" void kernel_launch(void* const* d_in, const int* in_sizes, int n_in,
                              void* d_out, int out_size) {
    const float* x    = (const float*)d_in[0];
    const float* W_ir = (const float*)d_in[1];
    const float* b_ir = (const float*)d_in[2];
    const float* W_hr = (const float*)d_in[3];
    const float* b_hr = (const float*)d_in[4];
    const float* W_iz = (const float*)d_in[5];
    const float* b_iz = (const float*)d_in[6];
    const float* W_hz = (const float*)d_in[7];
    const float* b_hz = (const float*)d_in[8];
    const float* W_in = (const float*)d_in[9];
    const float* b_in = (const float*)d_in[10];
    const float* W_hn = (const float*)d_in[11];
    const float* b_hn = (const float*)d_in[12];
    float* out = (float*)d_out;

    const int has_hfinal = ((size_t)out_size >= TBH + (size_t)BH) ? 1 : 0;

    static bool init_done = false;
    if (!init_done) {
        cudaFuncSetAttribute(fused_kernel,
                             cudaFuncAttributeMaxDynamicSharedMemorySize, FUSED_SMEM);
        init_done = true;
    }

    prep_kernel<<<38912, 256>>>(x, W_hr, W_hz, W_hn, W_ir, W_iz, W_in);
    fused_kernel<<<NTOT, NTHR, FUSED_SMEM>>>(b_ir, b_hr, b_iz, b_hz, b_in, b_hn,
                                             out, has_hfinal);
}